// round 11
// baseline (speedup 1.0000x reference)
#include <cuda_runtime.h>
#include <cuda_fp16.h>
#include <cstdint>

// Problem constants
#define OUT_F 4096
#define IN_F  4096
#define MROWS 8192
#define NPACK (OUT_F * IN_F / 2)

// GEMM tiling: CTA tile 128x128, 8 warps (2 M x 4 N), warp tile 64x32, KT=128
#define MT 128
#define NT 128
#define KT 128
#define NKT (IN_F / KT)              // 32 k-chunks per tile
#define HALF_BYTES (MT * 128)        // 16384
#define A_BYTES (2 * HALF_BYTES)     // 32768 per stage
#define SMEM_DYN (3 * A_BYTES)       // 98304 per CTA -> 2 CTAs/SM

#define NTILE_TOT 2048               // 32 n-tiles x 64 m-tiles
#define GRID_P 296                   // 2 CTAs x 148 SMs, persistent

// (n8, k16) B tiles
#define NTILES_N (OUT_F / 8)         // 512
#define NTILES_K (IN_F / 16)         // 256

// ---------------- scratch ------------------------------------------------------
__device__ uint2  g_wp[(size_t)NTILES_N * NTILES_K * 32];  // 32 MB: B fragment layout
__device__ __half g_x[(size_t)MROWS * IN_F];               // 64 MB: X as fp16
__device__ float  g_xsum[MROWS];

// ---------------- helpers ------------------------------------------------------
__device__ __forceinline__ uint32_t h2u(__half2 h) {
    __half2_raw r = *reinterpret_cast<__half2_raw*>(&h);
    return (uint32_t)r.x | ((uint32_t)r.y << 16);
}
__device__ __forceinline__ uint32_t s2u(const void* p) {
    uint32_t a;
    asm("{ .reg .u64 t; cvta.to.shared.u64 t, %1; cvt.u32.u64 %0, t; }" : "=r"(a) : "l"(p));
    return a;
}
__device__ __forceinline__ uint32_t swz(uint32_t off) { return off ^ ((off >> 3) & 0x70); }

__device__ __forceinline__ void cpa16(uint32_t dst, const void* src) {
    asm volatile("cp.async.cg.shared.global [%0], [%1], 16;" :: "r"(dst), "l"(src));
}
#define CP_COMMIT() asm volatile("cp.async.commit_group;" ::: "memory")
#define CP_WAIT1()  asm volatile("cp.async.wait_group 1;" ::: "memory")

__device__ __forceinline__ void ldm_x4(uint32_t* r, uint32_t addr) {
    asm volatile("ldmatrix.sync.aligned.m8n8.x4.shared.b16 {%0,%1,%2,%3}, [%4];"
                 : "=r"(r[0]), "=r"(r[1]), "=r"(r[2]), "=r"(r[3]) : "r"(addr));
}
__device__ __forceinline__ void mma16816(float* d, const uint32_t* a, const uint32_t* b) {
    asm volatile(
        "mma.sync.aligned.m16n8k16.row.col.f32.f16.f16.f32 "
        "{%0,%1,%2,%3}, {%4,%5,%6,%7}, {%8,%9}, {%0,%1,%2,%3};"
        : "+f"(d[0]), "+f"(d[1]), "+f"(d[2]), "+f"(d[3])
        : "r"(a[0]), "r"(a[1]), "r"(a[2]), "r"(a[3]), "r"(b[0]), "r"(b[1]));
}

// ---------------- merged prep ---------------------------------------------------
#define PREP_B_BLOCKS (NTILES_N * NTILES_K / 8)   // 16384
__global__ void prep(const float* __restrict__ x, const int* __restrict__ packed) {
    const int tid = threadIdx.x;
    if (blockIdx.x < MROWS) {
        const int row = blockIdx.x;
        const float4* xr = reinterpret_cast<const float4*>(x + (size_t)row * IN_F);
        uint2* dr = reinterpret_cast<uint2*>(g_x + (size_t)row * IN_F);
        float s = 0.f;
#pragma unroll
        for (int i = 0; i < 4; i++) {
            int j = i * 256 + tid;
            float4 v = xr[j];
            s += v.x + v.y + v.z + v.w;
            uint2 h;
            h.x = h2u(__floats2half2_rn(v.x, v.y));
            h.y = h2u(__floats2half2_rn(v.z, v.w));
            dr[j] = h;
        }
#pragma unroll
        for (int o = 16; o > 0; o >>= 1) s += __shfl_xor_sync(0xffffffffu, s, o);
        __shared__ float red[8];
        if ((tid & 31) == 0) red[tid >> 5] = s;
        __syncthreads();
        if (tid == 0) {
            float t = 0.f;
#pragma unroll
            for (int w = 0; w < 8; w++) t += red[w];
            g_xsum[row] = t;
        }
    } else {
        int tile = (blockIdx.x - MROWS) * 8 + (tid >> 5);
        int l = tid & 31;
        int tn = tile / NTILES_K;
        int tk = tile % NTILES_K;
        int n = tn * 8 + (l >> 2);
        int bi = n * (IN_F / 2) + tk * 8 + (l & 3);
        int b0 = packed[bi];
        int b1 = packed[bi + 4];
        uint2 o;
        o.x = h2u(__floats2half2_rn((float)((b0 << 28) >> 28), (float)((b0 << 24) >> 28)));
        o.y = h2u(__floats2half2_rn((float)((b1 << 28) >> 28), (float)((b1 << 24) >> 28)));
        g_wp[(size_t)tile * 32 + l] = o;
    }
}

// ------------------------------ persistent GEMM ----------------------------------
__global__ void __launch_bounds__(256, 2) gemm_q4(
    const float* __restrict__ scales, const float* __restrict__ zps,
    const float* __restrict__ bias, float* __restrict__ out)
{
    extern __shared__ char dyn_raw[];
    const uint32_t dynb = s2u(dyn_raw);

    const int tid = threadIdx.x;
    const int lane = tid & 31;
    const int wid = tid >> 5;
    const int warp_m = wid & 1;
    const int warp_n = wid >> 1;
    const int bx = blockIdx.x;

    const int my_tiles = (NTILE_TOT - 1 - bx) / GRID_P + 1;
    const int my_chunks = my_tiles * NKT;

    const int prow = tid >> 3;       // 0..31
    const int pcol = tid & 7;
    const uint32_t p_dst0 = swz((uint32_t)(prow * 128 + pcol * 16));

    // produce global chunk j (tile_seq = j/32, kt = j%32) into slot j%3
    auto produce = [&](int j) {
        if (j >= my_chunks) return;
        int t = bx + (j >> 5) * GRID_P;
        int kt = j & 31;
        int mb = (t & 63) * MT;
        const char* a_src = reinterpret_cast<const char*>(
            g_x + ((size_t)(mb + prow) * IN_F + pcol * 8)) + (size_t)kt * (KT * 2);
        uint32_t as = dynb + (j % 3) * A_BYTES;
#pragma unroll
        for (int h = 0; h < 2; h++)
#pragma unroll
            for (int i = 0; i < 4; i++)
                cpa16(as + h * HALF_BYTES + p_dst0 + i * 32 * 128,
                      a_src + h * 128 + (size_t)i * 32 * IN_F * 2);
    };

    produce(0); CP_COMMIT();
    produce(1); CP_COMMIT();

    const int a_lrow = lane & 15;
    const int a_lsel = lane >> 4;

    // B fragment pointer + prime for first tile
    const uint2* bptr = g_wp + ((size_t)((bx >> 6) * (NT / 8) + warp_n * 4) * NTILES_K) * 32 + lane;
    uint2 rbf[2][4];
#pragma unroll
    for (int jp = 0; jp < 4; jp++) rbf[0][jp] = bptr[(size_t)jp * NTILES_K * 32];

    for (int ts = 0; ts < my_tiles; ts++) {
        const int t = bx + ts * GRID_P;
        const int m_base = (t & 63) * MT;
        const int n_base = (t >> 6) * NT;

        float acc[4][4][4];
#pragma unroll
        for (int im = 0; im < 4; im++)
#pragma unroll
            for (int jn = 0; jn < 4; jn++)
#pragma unroll
                for (int r = 0; r < 4; r++) acc[im][jn][r] = 0.f;

        for (int kt = 0; kt < NKT; kt++) {
            const int j = ts * NKT + kt;
            CP_WAIT1();
            __syncthreads();
            produce(j + 2);          // crosses tile boundaries seamlessly
            CP_COMMIT();

            uint32_t as = dynb + (j % 3) * A_BYTES;

#pragma unroll
            for (int ks = 0; ks < 8; ks++) {
                const int tk = kt * 8 + ks;
                const int cur = tk & 1, nxt = cur ^ 1;
                if (tk + 1 < NTILES_K) {
#pragma unroll
                    for (int jp = 0; jp < 4; jp++)
                        rbf[nxt][jp] = bptr[((size_t)jp * NTILES_K + tk + 1) * 32];
                }
                uint32_t ra[4][4];
                const uint32_t ah = as + (ks >> 2) * HALF_BYTES;
                const int ksh = ks & 3;
#pragma unroll
                for (int im = 0; im < 4; im++) {
                    int r0 = warp_m * 64 + im * 16;
                    ldm_x4(ra[im], ah + swz((uint32_t)((r0 + a_lrow) * 128 + (2 * ksh + a_lsel) * 16)));
                }
#pragma unroll
                for (int im = 0; im < 4; im++)
#pragma unroll
                    for (int jn = 0; jn < 4; jn++)
                        mma16816(acc[im][jn], ra[im],
                                 reinterpret_cast<const uint32_t*>(&rbf[cur][jn]));
            }
        }

        // prime B for next tile before epilogue (L2 latency hidden by stores)
        if (ts + 1 < my_tiles) {
            int tn2 = (bx + (ts + 1) * GRID_P) >> 6;
            bptr = g_wp + ((size_t)(tn2 * (NT / 8) + warp_n * 4) * NTILES_K) * 32 + lane;
#pragma unroll
            for (int jp = 0; jp < 4; jp++) rbf[0][jp] = bptr[(size_t)jp * NTILES_K * 32];
        }

        // ---------------- epilogue: dequant + bias (no smem; overlaps cp.async) ----
        const int gid = lane >> 2;
        const int tg  = lane & 3;
        const int g   = n_base >> 7;
        const float sg = scales[g], zg = zps[g];
        const float szg = sg * zg;

#pragma unroll
        for (int im = 0; im < 4; im++) {
            int m0 = m_base + warp_m * 64 + im * 16 + gid;
            float xs0 = g_xsum[m0];
            float xs1 = g_xsum[m0 + 8];
            float sub0 = szg * xs0, sub1 = szg * xs1;
#pragma unroll
            for (int jn = 0; jn < 4; jn++) {
                int n0 = n_base + warp_n * 32 + jn * 8 + tg * 2;
                float b0 = bias[n0], b1 = bias[n0 + 1];

                float2 v0, v1;
                v0.x = sg * acc[im][jn][0] - sub0 + b0;
                v0.y = sg * acc[im][jn][1] - sub0 + b1;
                v1.x = sg * acc[im][jn][2] - sub1 + b0;
                v1.y = sg * acc[im][jn][3] - sub1 + b1;
                *reinterpret_cast<float2*>(out + (size_t)m0 * OUT_F + n0) = v0;
                *reinterpret_cast<float2*>(out + (size_t)(m0 + 8) * OUT_F + n0) = v1;
            }
        }
    }
}

// ------------------------------- launch -------------------------------------------
extern "C" void kernel_launch(void* const* d_in, const int* in_sizes, int n_in,
                              void* d_out, int out_size) {
    const float* x      = (const float*)d_in[0];
    const int*   packed = (const int*)d_in[1];
    const float* scales = (const float*)d_in[2];
    const float* zps    = (const float*)d_in[3];
    const float* bias   = (const float*)d_in[4];
    float* out = (float*)d_out;

    prep<<<MROWS + PREP_B_BLOCKS, 256>>>(x, packed);

    cudaFuncSetAttribute(gemm_q4, cudaFuncAttributeMaxDynamicSharedMemorySize, SMEM_DYN);
    gemm_q4<<<GRID_P, 256, SMEM_DYN>>>(scales, zps, bias, out);
}

// round 12
// speedup vs baseline: 1.0332x; 1.0332x over previous
#include <cuda_runtime.h>
#include <cuda_fp16.h>
#include <cstdint>

// Problem constants
#define OUT_F 4096
#define IN_F  4096
#define MROWS 8192
#define NPACK (OUT_F * IN_F / 2)

// GEMM tiling: CTA tile 128x128, 8 warps (2 M x 4 N), warp tile 64x32, KT=128
#define MT 128
#define NT 128
#define KT 128
#define NKT (IN_F / KT)              // 32 k-chunks per tile
#define HALF_BYTES (MT * 128)        // 16384
#define A_BYTES (2 * HALF_BYTES)     // 32768 per stage
#define SMEM_DYN (3 * A_BYTES)       // 98304 per CTA -> 2 CTAs/SM

#define NTILE_TOT 2048               // 64 m-tiles x 32 n-tiles
#define GRID_P 296                   // 2 CTAs x 148 SMs, persistent

// (n8, k16) B tiles
#define NTILES_N (OUT_F / 8)         // 512
#define NTILES_K (IN_F / 16)         // 256

// ---------------- scratch ------------------------------------------------------
__device__ uint2  g_wp[(size_t)NTILES_N * NTILES_K * 32];  // 32 MB: B fragment layout
__device__ __half g_x[(size_t)MROWS * IN_F];               // 64 MB: X as fp16
__device__ float  g_xsum[MROWS];

// ---------------- helpers ------------------------------------------------------
__device__ __forceinline__ uint32_t h2u(__half2 h) {
    __half2_raw r = *reinterpret_cast<__half2_raw*>(&h);
    return (uint32_t)r.x | ((uint32_t)r.y << 16);
}
__device__ __forceinline__ uint32_t s2u(const void* p) {
    uint32_t a;
    asm("{ .reg .u64 t; cvta.to.shared.u64 t, %1; cvt.u32.u64 %0, t; }" : "=r"(a) : "l"(p));
    return a;
}
__device__ __forceinline__ uint32_t swz(uint32_t off) { return off ^ ((off >> 3) & 0x70); }

__device__ __forceinline__ void cpa16(uint32_t dst, const void* src) {
    asm volatile("cp.async.cg.shared.global [%0], [%1], 16;" :: "r"(dst), "l"(src));
}
#define CP_COMMIT() asm volatile("cp.async.commit_group;" ::: "memory")
#define CP_WAIT1()  asm volatile("cp.async.wait_group 1;" ::: "memory")

__device__ __forceinline__ void ldm_x4(uint32_t* r, uint32_t addr) {
    asm volatile("ldmatrix.sync.aligned.m8n8.x4.shared.b16 {%0,%1,%2,%3}, [%4];"
                 : "=r"(r[0]), "=r"(r[1]), "=r"(r[2]), "=r"(r[3]) : "r"(addr));
}
__device__ __forceinline__ void mma16816(float* d, const uint32_t* a, const uint32_t* b) {
    asm volatile(
        "mma.sync.aligned.m16n8k16.row.col.f32.f16.f16.f32 "
        "{%0,%1,%2,%3}, {%4,%5,%6,%7}, {%8,%9}, {%0,%1,%2,%3};"
        : "+f"(d[0]), "+f"(d[1]), "+f"(d[2]), "+f"(d[3])
        : "r"(a[0]), "r"(a[1]), "r"(a[2]), "r"(a[3]), "r"(b[0]), "r"(b[1]));
}

// ---------------- merged prep ---------------------------------------------------
#define PREP_B_BLOCKS (NTILES_N * NTILES_K / 8)   // 16384
__global__ void prep(const float* __restrict__ x, const int* __restrict__ packed) {
    const int tid = threadIdx.x;
    if (blockIdx.x < MROWS) {
        const int row = blockIdx.x;
        const float4* xr = reinterpret_cast<const float4*>(x + (size_t)row * IN_F);
        uint2* dr = reinterpret_cast<uint2*>(g_x + (size_t)row * IN_F);
        float s = 0.f;
#pragma unroll
        for (int i = 0; i < 4; i++) {
            int j = i * 256 + tid;
            float4 v = xr[j];
            s += v.x + v.y + v.z + v.w;
            uint2 h;
            h.x = h2u(__floats2half2_rn(v.x, v.y));
            h.y = h2u(__floats2half2_rn(v.z, v.w));
            dr[j] = h;
        }
#pragma unroll
        for (int o = 16; o > 0; o >>= 1) s += __shfl_xor_sync(0xffffffffu, s, o);
        __shared__ float red[8];
        if ((tid & 31) == 0) red[tid >> 5] = s;
        __syncthreads();
        if (tid == 0) {
            float t = 0.f;
#pragma unroll
            for (int w = 0; w < 8; w++) t += red[w];
            g_xsum[row] = t;
        }
    } else {
        int tile = (blockIdx.x - MROWS) * 8 + (tid >> 5);
        int l = tid & 31;
        int tn = tile / NTILES_K;
        int tk = tile % NTILES_K;
        int n = tn * 8 + (l >> 2);
        int bi = n * (IN_F / 2) + tk * 8 + (l & 3);
        int b0 = packed[bi];
        int b1 = packed[bi + 4];
        uint2 o;
        o.x = h2u(__floats2half2_rn((float)((b0 << 28) >> 28), (float)((b0 << 24) >> 28)));
        o.y = h2u(__floats2half2_rn((float)((b1 << 28) >> 28), (float)((b1 << 24) >> 28)));
        g_wp[(size_t)tile * 32 + l] = o;
    }
}

// ------------------------------ persistent GEMM ----------------------------------
// tile index τ is n-FAST: m = τ>>5, n = τ&31 — concurrent window spans ~10 m-blocks
__global__ void __launch_bounds__(256, 2) gemm_q4(
    const float* __restrict__ scales, const float* __restrict__ zps,
    const float* __restrict__ bias, float* __restrict__ out)
{
    extern __shared__ char dyn_raw[];
    const uint32_t dynb = s2u(dyn_raw);

    const int tid = threadIdx.x;
    const int lane = tid & 31;
    const int wid = tid >> 5;
    const int warp_m = wid & 1;
    const int warp_n = wid >> 1;
    const int bx = blockIdx.x;

    const int my_tiles = (NTILE_TOT - 1 - bx) / GRID_P + 1;
    const int my_chunks = my_tiles * NKT;

    const int prow = tid >> 3;       // 0..31
    const int pcol = tid & 7;
    const uint32_t p_dst0 = swz((uint32_t)(prow * 128 + pcol * 16));

    // produce global chunk j (tile_seq = j/32, kt = j%32) into slot j%3
    auto produce = [&](int j) {
        if (j >= my_chunks) return;
        int t = bx + (j >> 5) * GRID_P;
        int kt = j & 31;
        int mb = (t >> 5) * MT;                   // n-fast mapping
        const char* a_src = reinterpret_cast<const char*>(
            g_x + ((size_t)(mb + prow) * IN_F + pcol * 8)) + (size_t)kt * (KT * 2);
        uint32_t as = dynb + (j % 3) * A_BYTES;
#pragma unroll
        for (int h = 0; h < 2; h++)
#pragma unroll
            for (int i = 0; i < 4; i++)
                cpa16(as + h * HALF_BYTES + p_dst0 + i * 32 * 128,
                      a_src + h * 128 + (size_t)i * 32 * IN_F * 2);
    };

    produce(0); CP_COMMIT();
    produce(1); CP_COMMIT();

    const int a_lrow = lane & 15;
    const int a_lsel = lane >> 4;

    // B fragment pointer + prime for first tile (n = bx & 31)
    const uint2* bptr = g_wp + ((size_t)((bx & 31) * (NT / 8) + warp_n * 4) * NTILES_K) * 32 + lane;
    uint2 rbf[2][4];
#pragma unroll
    for (int jp = 0; jp < 4; jp++) rbf[0][jp] = bptr[(size_t)jp * NTILES_K * 32];

    for (int ts = 0; ts < my_tiles; ts++) {
        const int t = bx + ts * GRID_P;
        const int m_base = (t >> 5) * MT;
        const int n_base = (t & 31) * NT;

        float acc[4][4][4];
#pragma unroll
        for (int im = 0; im < 4; im++)
#pragma unroll
            for (int jn = 0; jn < 4; jn++)
#pragma unroll
                for (int r = 0; r < 4; r++) acc[im][jn][r] = 0.f;

        for (int kt = 0; kt < NKT; kt++) {
            const int j = ts * NKT + kt;
            CP_WAIT1();
            __syncthreads();
            produce(j + 2);          // crosses tile boundaries seamlessly
            CP_COMMIT();

            uint32_t as = dynb + (j % 3) * A_BYTES;

#pragma unroll
            for (int ks = 0; ks < 8; ks++) {
                const int tk = kt * 8 + ks;
                const int cur = tk & 1, nxt = cur ^ 1;
                if (tk + 1 < NTILES_K) {
#pragma unroll
                    for (int jp = 0; jp < 4; jp++)
                        rbf[nxt][jp] = bptr[((size_t)jp * NTILES_K + tk + 1) * 32];
                }
                uint32_t ra[4][4];
                const uint32_t ah = as + (ks >> 2) * HALF_BYTES;
                const int ksh = ks & 3;
#pragma unroll
                for (int im = 0; im < 4; im++) {
                    int r0 = warp_m * 64 + im * 16;
                    ldm_x4(ra[im], ah + swz((uint32_t)((r0 + a_lrow) * 128 + (2 * ksh + a_lsel) * 16)));
                }
#pragma unroll
                for (int im = 0; im < 4; im++)
#pragma unroll
                    for (int jn = 0; jn < 4; jn++)
                        mma16816(acc[im][jn], ra[im],
                                 reinterpret_cast<const uint32_t*>(&rbf[cur][jn]));
            }
        }

        // prime B for next tile before epilogue (L2 latency hidden by stores)
        if (ts + 1 < my_tiles) {
            int tn2 = (bx + (ts + 1) * GRID_P) & 31;
            bptr = g_wp + ((size_t)(tn2 * (NT / 8) + warp_n * 4) * NTILES_K) * 32 + lane;
#pragma unroll
            for (int jp = 0; jp < 4; jp++) rbf[0][jp] = bptr[(size_t)jp * NTILES_K * 32];
        }

        // ---------------- epilogue: dequant + bias (overlaps in-flight cp.async) ---
        const int gid = lane >> 2;
        const int tg  = lane & 3;
        const int g   = n_base >> 7;
        const float sg = scales[g], zg = zps[g];
        const float szg = sg * zg;

#pragma unroll
        for (int im = 0; im < 4; im++) {
            int m0 = m_base + warp_m * 64 + im * 16 + gid;
            float xs0 = g_xsum[m0];
            float xs1 = g_xsum[m0 + 8];
            float sub0 = szg * xs0, sub1 = szg * xs1;
#pragma unroll
            for (int jn = 0; jn < 4; jn++) {
                int n0 = n_base + warp_n * 32 + jn * 8 + tg * 2;
                float b0 = bias[n0], b1 = bias[n0 + 1];

                float2 v0, v1;
                v0.x = sg * acc[im][jn][0] - sub0 + b0;
                v0.y = sg * acc[im][jn][1] - sub0 + b1;
                v1.x = sg * acc[im][jn][2] - sub1 + b0;
                v1.y = sg * acc[im][jn][3] - sub1 + b1;
                *reinterpret_cast<float2*>(out + (size_t)m0 * OUT_F + n0) = v0;
                *reinterpret_cast<float2*>(out + (size_t)(m0 + 8) * OUT_F + n0) = v1;
            }
        }
    }
}

// ------------------------------- launch -------------------------------------------
extern "C" void kernel_launch(void* const* d_in, const int* in_sizes, int n_in,
                              void* d_out, int out_size) {
    const float* x      = (const float*)d_in[0];
    const int*   packed = (const int*)d_in[1];
    const float* scales = (const float*)d_in[2];
    const float* zps    = (const float*)d_in[3];
    const float* bias   = (const float*)d_in[4];
    float* out = (float*)d_out;

    prep<<<MROWS + PREP_B_BLOCKS, 256>>>(x, packed);

    cudaFuncSetAttribute(gemm_q4, cudaFuncAttributeMaxDynamicSharedMemorySize, SMEM_DYN);
    gemm_q4<<<GRID_P, 256, SMEM_DYN>>>(scales, zps, bias, out);
}

// round 13
// speedup vs baseline: 1.1159x; 1.0800x over previous
#include <cuda_runtime.h>
#include <cuda_fp16.h>
#include <cstdint>

// Problem constants
#define OUT_F 4096
#define IN_F  4096
#define MROWS 8192
#define NPACK (OUT_F * IN_F / 2)

// (m16/n8, k16) fragment tiles
#define MTILES   (MROWS / 16)        // 512
#define NTILES_N (OUT_F / 8)         // 512
#define NTILES_K (IN_F / 16)         // 256

// GEMM: CTA covers 128x128, 8 warps (2 M x 4 N), warp tile 64x32. No smem.
#define MT 128
#define NT 128

// ---------------- scratch ------------------------------------------------------
__device__ uint4  g_xa[(size_t)MTILES * NTILES_K * 32];    // 64 MB: A fragment layout
__device__ uint2  g_wp[(size_t)NTILES_N * NTILES_K * 32];  // 32 MB: B fragment layout
__device__ float  g_xsum[MROWS];

// ---------------- helpers ------------------------------------------------------
__device__ __forceinline__ uint32_t h2u(__half2 h) {
    __half2_raw r = *reinterpret_cast<__half2_raw*>(&h);
    return (uint32_t)r.x | ((uint32_t)r.y << 16);
}
__device__ __forceinline__ void mma16816(float* d, const uint32_t* a, const uint32_t* b) {
    asm volatile(
        "mma.sync.aligned.m16n8k16.row.col.f32.f16.f16.f32 "
        "{%0,%1,%2,%3}, {%4,%5,%6,%7}, {%8,%9}, {%0,%1,%2,%3};"
        : "+f"(d[0]), "+f"(d[1]), "+f"(d[2]), "+f"(d[3])
        : "r"(a[0]), "r"(a[1]), "r"(a[2]), "r"(a[3]), "r"(b[0]), "r"(b[1]));
}

// ---------------- prep ----------------------------------------------------------
// blocks [0, 512): A fragments + row sums for m16 band mt = blockIdx.x
// blocks [512, 512+16384): B permute
#define PREP_A_BLOCKS MTILES                       // 512
#define PREP_B_BLOCKS (NTILES_N * NTILES_K / 8)    // 16384
__global__ void prep(const float* __restrict__ x, const int* __restrict__ packed) {
    const int tid = threadIdx.x;
    const int w = tid >> 5;
    const int l = tid & 31;
    if (blockIdx.x < PREP_A_BLOCKS) {
        const int mt = blockIdx.x;
        const int gid = l >> 2;          // 0..7
        const int c   = l & 3;           // 0..3
        const int r0 = mt * 16 + gid;
        const int r1 = r0 + 8;
        const float* xr0 = x + (size_t)r0 * IN_F;
        const float* xr1 = x + (size_t)r1 * IN_F;
        float s0 = 0.f, s1 = 0.f;
        // warp w handles k16 tiles tk = w + 8*j
        for (int j = 0; j < NTILES_K / 8; j++) {
            int tk = w + 8 * j;
            int k0 = tk * 16 + 2 * c;
            float2 v00 = *reinterpret_cast<const float2*>(xr0 + k0);
            float2 v10 = *reinterpret_cast<const float2*>(xr1 + k0);
            float2 v01 = *reinterpret_cast<const float2*>(xr0 + k0 + 8);
            float2 v11 = *reinterpret_cast<const float2*>(xr1 + k0 + 8);
            s0 += v00.x + v00.y + v01.x + v01.y;
            s1 += v10.x + v10.y + v11.x + v11.y;
            uint4 o;
            o.x = h2u(__floats2half2_rn(v00.x, v00.y));
            o.y = h2u(__floats2half2_rn(v10.x, v10.y));
            o.z = h2u(__floats2half2_rn(v01.x, v01.y));
            o.w = h2u(__floats2half2_rn(v11.x, v11.y));
            g_xa[((size_t)mt * NTILES_K + tk) * 32 + l] = o;
        }
        // reduce over c within quad
        s0 += __shfl_xor_sync(0xffffffffu, s0, 1);
        s0 += __shfl_xor_sync(0xffffffffu, s0, 2);
        s1 += __shfl_xor_sync(0xffffffffu, s1, 1);
        s1 += __shfl_xor_sync(0xffffffffu, s1, 2);
        __shared__ float red[8][16];
        if (c == 0) { red[w][gid] = s0; red[w][gid + 8] = s1; }
        __syncthreads();
        if (tid < 16) {
            float t = 0.f;
#pragma unroll
            for (int ww = 0; ww < 8; ww++) t += red[ww][tid];
            g_xsum[mt * 16 + tid] = t;
        }
    } else {
        int tile = (blockIdx.x - PREP_A_BLOCKS) * 8 + w;
        int tn = tile / NTILES_K;
        int tk = tile % NTILES_K;
        int n = tn * 8 + (l >> 2);
        int bi = n * (IN_F / 2) + tk * 8 + (l & 3);
        int b0 = packed[bi];
        int b1 = packed[bi + 4];
        uint2 o;
        o.x = h2u(__floats2half2_rn((float)((b0 << 28) >> 28), (float)((b0 << 24) >> 28)));
        o.y = h2u(__floats2half2_rn((float)((b1 << 28) >> 28), (float)((b1 << 24) >> 28)));
        g_wp[(size_t)tile * 32 + l] = o;
    }
}

// ------------------------------ barrier-free GEMM --------------------------------
__global__ void __launch_bounds__(256, 2) gemm_q4(
    const float* __restrict__ scales, const float* __restrict__ zps,
    const float* __restrict__ bias, float* __restrict__ out)
{
    const int tid = threadIdx.x;
    const int lane = tid & 31;
    const int wid = tid >> 5;
    const int warp_m = wid & 1;      // 2 warps along M -> 64 rows (4 m16 tiles)
    const int warp_n = wid >> 1;     // 4 warps along N -> 32 cols (4 n8 tiles)
    const int m_base = blockIdx.y * MT;
    const int n_base = blockIdx.x * NT;

    // fragment base pointers (lane-resolved)
    const int mt0 = (m_base >> 4) + warp_m * 4;
    const int tn0 = (n_base >> 3) + warp_n * 4;
    const uint4* ap = g_xa + ((size_t)mt0 * NTILES_K) * 32 + lane;
    const uint2* bp = g_wp + ((size_t)tn0 * NTILES_K) * 32 + lane;
    // per-tile strides (in elements): A: im -> NTILES_K*32 ; tk -> 32
    //                                 B: jp -> NTILES_K*32 ; tk -> 32

    float acc[4][4][4];
#pragma unroll
    for (int im = 0; im < 4; im++)
#pragma unroll
        for (int jn = 0; jn < 4; jn++)
#pragma unroll
            for (int r = 0; r < 4; r++) acc[im][jn][r] = 0.f;

    uint4 raf[2][4];
    uint2 rbf[2][4];
#pragma unroll
    for (int im = 0; im < 4; im++) raf[0][im] = ap[(size_t)im * NTILES_K * 32];
#pragma unroll
    for (int jp = 0; jp < 4; jp++) rbf[0][jp] = bp[(size_t)jp * NTILES_K * 32];

#pragma unroll 4
    for (int tk = 0; tk < NTILES_K; tk++) {
        const int cur = tk & 1, nxt = cur ^ 1;
        if (tk + 1 < NTILES_K) {
            const uint4* ap1 = ap + (size_t)(tk + 1) * 32;
            const uint2* bp1 = bp + (size_t)(tk + 1) * 32;
#pragma unroll
            for (int im = 0; im < 4; im++) raf[nxt][im] = ap1[(size_t)im * NTILES_K * 32];
#pragma unroll
            for (int jp = 0; jp < 4; jp++) rbf[nxt][jp] = bp1[(size_t)jp * NTILES_K * 32];
        }
#pragma unroll
        for (int im = 0; im < 4; im++)
#pragma unroll
            for (int jn = 0; jn < 4; jn++)
                mma16816(acc[im][jn],
                         reinterpret_cast<const uint32_t*>(&raf[cur][im]),
                         reinterpret_cast<const uint32_t*>(&rbf[cur][jn]));
    }

    // ---------------- epilogue: dequant + bias ------------------------------------
    const int gid = lane >> 2;
    const int tg  = lane & 3;
    const int g   = n_base >> 7;
    const float sg = scales[g], zg = zps[g];
    const float szg = sg * zg;

#pragma unroll
    for (int im = 0; im < 4; im++) {
        int m0 = m_base + warp_m * 64 + im * 16 + gid;
        float xs0 = g_xsum[m0];
        float xs1 = g_xsum[m0 + 8];
        float sub0 = szg * xs0, sub1 = szg * xs1;
#pragma unroll
        for (int jn = 0; jn < 4; jn++) {
            int n0 = n_base + warp_n * 32 + jn * 8 + tg * 2;
            float b0 = bias[n0], b1 = bias[n0 + 1];

            float2 v0, v1;
            v0.x = sg * acc[im][jn][0] - sub0 + b0;
            v0.y = sg * acc[im][jn][1] - sub0 + b1;
            v1.x = sg * acc[im][jn][2] - sub1 + b0;
            v1.y = sg * acc[im][jn][3] - sub1 + b1;
            *reinterpret_cast<float2*>(out + (size_t)m0 * OUT_F + n0) = v0;
            *reinterpret_cast<float2*>(out + (size_t)(m0 + 8) * OUT_F + n0) = v1;
        }
    }
}

// ------------------------------- launch -------------------------------------------
extern "C" void kernel_launch(void* const* d_in, const int* in_sizes, int n_in,
                              void* d_out, int out_size) {
    const float* x      = (const float*)d_in[0];
    const int*   packed = (const int*)d_in[1];
    const float* scales = (const float*)d_in[2];
    const float* zps    = (const float*)d_in[3];
    const float* bias   = (const float*)d_in[4];
    float* out = (float*)d_out;

    prep<<<PREP_A_BLOCKS + PREP_B_BLOCKS, 256>>>(x, packed);

    dim3 grid(OUT_F / NT, MROWS / MT);   // (32, 64), n-fast for A L2 locality
    gemm_q4<<<grid, 256>>>(scales, zps, bias, out);
}